// round 7
// baseline (speedup 1.0000x reference)
#include <cuda_runtime.h>
#include <cuda_fp16.h>
#include <cstdint>

#define B_  32
#define N_  2048
#define K_  128
#define CI_ 16
#define CO_ 16
#define KD_ (K_*CO_)   // 2048

typedef unsigned long long ull;

// XOR swizzle: permutes 16B cells within 1KB atoms -> conflict-free
#define SW(o) ((o) ^ (((o) >> 3) & 0x70))

// cp.async helpers
#define CP_ASYNC16(saddr, gptr) \
    asm volatile("cp.async.cg.shared.global [%0], [%1], 16;" :: "r"(saddr), "l"(gptr))
#define CP_COMMIT() asm volatile("cp.async.commit_group;")
#define CP_WAIT0()  asm volatile("cp.async.wait_group 0;" ::: "memory")

// ---------------- scratch ----------------
// u_hat stored batch-PAIR-interleaved: [bp][i][k][d] of half2 = (u[2bp], u[2bp+1])
__device__ __half2 g_uhat[(size_t)(B_/2) * N_ * KD_];   // 268MB
__device__ float   g_t[3][B_ * KD_];
__device__ float   g_S[2][B_ * K_];
__device__ float   g_v[2][B_ * KD_];
__device__ float   g_vn[2][B_ * K_];

// ---------------- f32x2 packed helpers ----------------
__device__ __forceinline__ ull pack2(float a, float b) {
    ull r; asm("mov.b64 %0, {%1,%2};" : "=l"(r) : "f"(a), "f"(b)); return r;
}
__device__ __forceinline__ void unpack2(ull v, float& a, float& b) {
    asm("mov.b64 {%0,%1}, %2;" : "=f"(a), "=f"(b) : "l"(v));
}
__device__ __forceinline__ void ffma2(ull& d, ull a, ull b) {
    asm("fma.rn.f32x2 %0, %1, %2, %0;" : "+l"(d) : "l"(a), "l"(b));
}
__device__ __forceinline__ void fadd2(ull& d, ull a) {
    asm("add.rn.f32x2 %0, %0, %1;" : "+l"(d) : "l"(a));
}
__device__ __forceinline__ __half2 shfl_h2(__half2 v, int m) {
    uint32_t u = *(uint32_t*)&v;
    u = __shfl_xor_sync(0xffffffffu, u, m);
    return *(__half2*)&u;
}

// labels dtype-agnostic (int32 vs int64); labels = arange(128)
__device__ __forceinline__ int load_label(const void* labels, int k) {
    const int* p32 = (const int*)labels;
    if (p32[1] == 1) return p32[k];
    return (int)((const long long*)labels)[k];
}

// ---------------- init ----------------
__global__ void k_init() {
    int idx = blockIdx.x * 256 + threadIdx.x;
    if (idx < 3 * B_ * KD_) (&g_t[0][0])[idx] = 0.f;
    if (idx < 2 * B_ * K_)  (&g_S[0][0])[idx] = 0.f;
}

// ---------------- pass 1 ----------------
__global__ void __launch_bounds__(256, 2) k_pass1(const float* __restrict__ x,
                                                  const void* __restrict__ labels,
                                                  const float* __restrict__ W1) {
    __shared__ __align__(16) float xs[16 * 512];   // [i][(bp*16+c)*2 + (b&1)]
    const int tid = threadIdx.x;
    const int kd  = blockIdx.y * 256 + tid;        // 0..2047
    const int k   = kd >> 4;
    const int d   = kd & 15;
    int ksrc = load_label(labels, k);
    if ((unsigned)ksrc >= (unsigned)K_) ksrc = k;
    const int i0  = blockIdx.x * 16;

    for (int e = tid; e < 8192; e += 256) {
        const int b = e >> 8, rem = e & 255, i = rem >> 4, c = rem & 15;
        xs[i * 512 + ((b >> 1) * 16 + c) * 2 + (b & 1)] =
            x[((size_t)b * N_ + i0 + i) * CI_ + c];
    }
    __syncthreads();

    ull tsum[16];
#pragma unroll
    for (int bp = 0; bp < 16; bp++) tsum[bp] = 0ull;

    const size_t wstride4 = (size_t)K_ * CO_ * CI_ / 4;
    const float4* wp = reinterpret_cast<const float4*>(
        W1 + (((size_t)i0 * K_ + ksrc) * CO_ + d) * CI_);

    float4 cw0 = wp[0], cw1 = wp[1], cw2 = wp[2], cw3 = wp[3];
    const float4* np1 = wp + wstride4;
    float4 nw0 = np1[0], nw1 = np1[1], nw2 = np1[2], nw3 = np1[3];

    for (int ii = 0; ii < 16; ii++) {
        float4 mw0, mw1, mw2, mw3;
        if (ii < 14) {
            const float4* np = wp + (size_t)(ii + 2) * wstride4;
            mw0 = np[0]; mw1 = np[1]; mw2 = np[2]; mw3 = np[3];
        }
        ull wd[16];
        wd[0]=pack2(cw0.x,cw0.x); wd[1]=pack2(cw0.y,cw0.y); wd[2]=pack2(cw0.z,cw0.z); wd[3]=pack2(cw0.w,cw0.w);
        wd[4]=pack2(cw1.x,cw1.x); wd[5]=pack2(cw1.y,cw1.y); wd[6]=pack2(cw1.z,cw1.z); wd[7]=pack2(cw1.w,cw1.w);
        wd[8]=pack2(cw2.x,cw2.x); wd[9]=pack2(cw2.y,cw2.y); wd[10]=pack2(cw2.z,cw2.z); wd[11]=pack2(cw2.w,cw2.w);
        wd[12]=pack2(cw3.x,cw3.x); wd[13]=pack2(cw3.y,cw3.y); wd[14]=pack2(cw3.z,cw3.z); wd[15]=pack2(cw3.w,cw3.w);

        const int i = i0 + ii;
        __half2* ubase = g_uhat + (size_t)i * KD_ + kd;
#pragma unroll
        for (int bp = 0; bp < 16; bp++) {
            const ulonglong2* xq = reinterpret_cast<const ulonglong2*>(xs + ii * 512 + bp * 32);
            ulonglong2 p0 = xq[0], p1 = xq[1], p2 = xq[2], p3 = xq[3];
            ulonglong2 p4 = xq[4], p5 = xq[5], p6 = xq[6], p7 = xq[7];
            ull acc0 = 0ull, acc1 = 0ull;
            ffma2(acc0, wd[0],  p0.x); ffma2(acc1, wd[1],  p0.y);
            ffma2(acc0, wd[2],  p1.x); ffma2(acc1, wd[3],  p1.y);
            ffma2(acc0, wd[4],  p2.x); ffma2(acc1, wd[5],  p2.y);
            ffma2(acc0, wd[6],  p3.x); ffma2(acc1, wd[7],  p3.y);
            ffma2(acc0, wd[8],  p4.x); ffma2(acc1, wd[9],  p4.y);
            ffma2(acc0, wd[10], p5.x); ffma2(acc1, wd[11], p5.y);
            ffma2(acc0, wd[12], p6.x); ffma2(acc1, wd[13], p6.y);
            ffma2(acc0, wd[14], p7.x); ffma2(acc1, wd[15], p7.y);
            fadd2(acc0, acc1);
            fadd2(tsum[bp], acc0);
            float lo, hi; unpack2(acc0, lo, hi);
            ubase[(size_t)bp * N_ * KD_] = __floats2half2_rn(lo, hi);   // one STG.32
        }
        cw0 = nw0; cw1 = nw1; cw2 = nw2; cw3 = nw3;
        nw0 = mw0; nw1 = mw1; nw2 = mw2; nw3 = mw3;
    }
#pragma unroll
    for (int bp = 0; bp < 16; bp++) {
        float a, bb; unpack2(tsum[bp], a, bb);
        atomicAdd(&g_t[0][(2 * bp)     * KD_ + kd], a);
        atomicAdd(&g_t[0][(2 * bp + 1) * KD_ + kd], bb);
    }
}

// ---------------- finalize ----------------
__global__ void k_finalize(int which) {
    const int idx = blockIdx.x * 256 + threadIdx.x;   // b*K + k
    const float* t = g_t[which];
    float inv = (which == 0) ? (1.0f / 2048.0f) : (1.0f / g_S[0][idx]);
    const float4* tp = reinterpret_cast<const float4*>(t + idx * 16);
    float w[16]; float s2 = 0.f;
#pragma unroll
    for (int q = 0; q < 4; q++) {
        float4 tv = tp[q];
        w[q*4+0]=tv.x*inv; w[q*4+1]=tv.y*inv; w[q*4+2]=tv.z*inv; w[q*4+3]=tv.w*inv;
        s2 += w[q*4+0]*w[q*4+0] + w[q*4+1]*w[q*4+1] + w[q*4+2]*w[q*4+2] + w[q*4+3]*w[q*4+3];
    }
    float sc = sqrtf(s2) / (0.5f + s2);
    float4* vp = reinterpret_cast<float4*>(g_v[which] + idx * 16);
#pragma unroll
    for (int q = 0; q < 4; q++) {
        float4 o; o.x=sc*w[q*4+0]; o.y=sc*w[q*4+1]; o.z=sc*w[q*4+2]; o.w=sc*w[q*4+3];
        vp[q] = o;
    }
    g_vn[which][idx] = sc * sc * s2;
}

// ---------------- routing pass: b-pair SIMD, one 8-i group per CTA --------------
// grid 4096 = 16 bpairs * 256 groups; block 256 (8 warps, warp w owns i0+w).
template <int IT>
__global__ void __launch_bounds__(256, 2) k_route() {
    extern __shared__ __align__(1024) char base[];
    char*    ub   = base;                          // 8 * 8KB u-pair slices (swizzled)
    __half2* cke  = (__half2*)(base + 65536);      // [8][128] packed (c_b0,c_b1)
    float2*  vnp  = (float2*)(base + 69632);       // [128]
    char*    v1p  = base + 70656;                  // 8KB half2 v0-pair (swizzled)
    float2*  vn2p = (float2*)(base + 78848);       // IT3
    char*    v2p  = base + 79872;                  // IT3: 8KB

    const int tid = threadIdx.x, lane = tid & 31, warp = tid >> 5;
    const int bp = blockIdx.x >> 8;
    const int g  = blockIdx.x & 255;
    const int b0 = 2 * bp, b1 = 2 * bp + 1;
    const int i0 = g * 8;

    // issue u staging (own warp slice, 8KB) immediately
    const uint32_t ub_s = (uint32_t)__cvta_generic_to_shared(ub);
    {
        const char* src = (const char*)(g_uhat + ((size_t)bp * N_ + i0 + warp) * KD_);
        uint32_t dst = ub_s + warp * 8192;
#pragma unroll
        for (int c = 0; c < 16; c++) {
            int off = (c * 32 + lane) * 16;
            CP_ASYNC16(dst + SW(off), src + off);
        }
        CP_COMMIT();
    }
    // stage v as (b0,b1)-pair half2 (overlaps the cp.async transfers)
    for (int e = tid; e < 2048; e += 256) {
        *(__half2*)(v1p + SW(e * 4)) =
            __floats2half2_rn(g_v[0][b0 * KD_ + e], g_v[0][b1 * KD_ + e]);
        if (IT == 3)
            *(__half2*)(v2p + SW(e * 4)) =
                __floats2half2_rn(g_v[1][b0 * KD_ + e], g_v[1][b1 * KD_ + e]);
    }
    if (tid < 128) {
        vnp[tid] = make_float2(g_vn[0][b0 * K_ + tid], g_vn[0][b1 * K_ + tid]);
        if (IT == 3) vn2p[tid] = make_float2(g_vn[1][b0 * K_ + tid], g_vn[1][b1 * K_ + tid]);
    }
    CP_WAIT0();
    __syncthreads();

    // ---- phase A: own i, both b at once (half2 lanes) ----
    const char* msl = ub + warp * 8192;
    float2 lg[4];
#pragma unroll
    for (int j = 0; j < 4; j++) {
        const int k = lane + 32 * j;
        const int ko = k * 64;
        uint4 r0 = *(const uint4*)(msl + SW(ko));
        uint4 r1 = *(const uint4*)(msl + SW(ko + 16));
        uint4 r2 = *(const uint4*)(msl + SW(ko + 32));
        uint4 r3 = *(const uint4*)(msl + SW(ko + 48));
        uint4 w0 = *(const uint4*)(v1p + SW(ko));
        uint4 w1 = *(const uint4*)(v1p + SW(ko + 16));
        uint4 w2 = *(const uint4*)(v1p + SW(ko + 32));
        uint4 w3 = *(const uint4*)(v1p + SW(ko + 48));
        const __half2* u2 = (const __half2*)&r0;   // r0..r3 contiguous on stack
        __half2 ureg[16], vreg[16];
        { const __half2* p = (const __half2*)&r0; for (int m=0;m<4;m++) ureg[m]    = p[m]; }
        { const __half2* p = (const __half2*)&r1; for (int m=0;m<4;m++) ureg[4+m]  = p[m]; }
        { const __half2* p = (const __half2*)&r2; for (int m=0;m<4;m++) ureg[8+m]  = p[m]; }
        { const __half2* p = (const __half2*)&r3; for (int m=0;m<4;m++) ureg[12+m] = p[m]; }
        { const __half2* p = (const __half2*)&w0; for (int m=0;m<4;m++) vreg[m]    = p[m]; }
        { const __half2* p = (const __half2*)&w1; for (int m=0;m<4;m++) vreg[4+m]  = p[m]; }
        { const __half2* p = (const __half2*)&w2; for (int m=0;m<4;m++) vreg[8+m]  = p[m]; }
        { const __half2* p = (const __half2*)&w3; for (int m=0;m<4;m++) vreg[12+m] = p[m]; }
        (void)u2;
        __half2 s2h = __hmul2(ureg[0], ureg[0]);
        __half2 d1h = __hmul2(ureg[0], vreg[0]);
#pragma unroll
        for (int m = 1; m < 16; m++) {
            s2h = __hfma2(ureg[m], ureg[m], s2h);
            d1h = __hfma2(ureg[m], vreg[m], d1h);
        }
        float2 dot2 = make_float2(0.f, 0.f);
        if (IT == 3) {
            uint4 y0 = *(const uint4*)(v2p + SW(ko));
            uint4 y1 = *(const uint4*)(v2p + SW(ko + 16));
            uint4 y2 = *(const uint4*)(v2p + SW(ko + 32));
            uint4 y3 = *(const uint4*)(v2p + SW(ko + 48));
            __half2 wreg[16];
            { const __half2* p = (const __half2*)&y0; for (int m=0;m<4;m++) wreg[m]    = p[m]; }
            { const __half2* p = (const __half2*)&y1; for (int m=0;m<4;m++) wreg[4+m]  = p[m]; }
            { const __half2* p = (const __half2*)&y2; for (int m=0;m<4;m++) wreg[8+m]  = p[m]; }
            { const __half2* p = (const __half2*)&y3; for (int m=0;m<4;m++) wreg[12+m] = p[m]; }
            __half2 d2h = __hmul2(ureg[0], wreg[0]);
#pragma unroll
            for (int m = 1; m < 16; m++) d2h = __hfma2(ureg[m], wreg[m], d2h);
            dot2 = __half22float2(d2h);
        }
        float2 s2f = __half22float2(s2h);
        float2 d1f = __half22float2(d1h);
        float2 vn  = vnp[k];
        float sca = sqrtf(s2f.x) / (0.5f + s2f.x);
        float scb = sqrtf(s2f.y) / (0.5f + s2f.y);
        float usqa = sca * sca * s2f.x;
        float usqb = scb * scb * s2f.y;
        float dda = 1.f - (usqa - 2.f * sca * d1f.x + vn.x);
        float ddb = 1.f - (usqb - 2.f * scb * d1f.y + vn.y);
        if (IT == 3) {
            float2 vn2 = vn2p[k];
            dda += 1.f - (usqa - 2.f * sca * dot2.x + vn2.x);
            ddb += 1.f - (usqb - 2.f * scb * dot2.y + vn2.y);
        }
        lg[j] = make_float2(dda, ddb);
    }

    // ---- packed softmax over 128 k for both b ----
    __half2 hl[4];
#pragma unroll
    for (int j = 0; j < 4; j++) hl[j] = __floats2half2_rn(lg[j].x, lg[j].y);
    __half2 hm = __hmax2(__hmax2(hl[0], hl[1]), __hmax2(hl[2], hl[3]));
#pragma unroll
    for (int o = 16; o > 0; o >>= 1) hm = __hmax2(hm, shfl_h2(hm, o));
#pragma unroll
    for (int j = 0; j < 4; j++) hl[j] = h2exp(__hsub2(hl[j], hm));
    __half2 es = __hadd2(__hadd2(hl[0], hl[1]), __hadd2(hl[2], hl[3]));
#pragma unroll
    for (int o = 16; o > 0; o >>= 1) es = __hadd2(es, shfl_h2(es, o));
    float2 ef = __half22float2(es);
    __half2 rinv = __floats2half2_rn(1.f / ef.x, 1.f / ef.y);
#pragma unroll
    for (int j = 0; j < 4; j++)
        cke[warp * 128 + lane + 32 * j] = __hmul2(hl[j], rinv);

    __syncthreads();

    // ---- phase B: f32x2 accumulation over the 8 i ----
    const int myk = warp * 16 + (lane >> 1);
    const int mo  = warp * 1024 + lane * 32;
    ull ta[8];
#pragma unroll
    for (int m = 0; m < 8; m++) ta[m] = 0ull;
    __half2 sh = __float2half2_rn(0.f);
#pragma unroll
    for (int i8 = 0; i8 < 8; i8++) {
        __half2 c2 = cke[i8 * 128 + myk];
        float2 cf = __half22float2(c2);
        ull cp = pack2(cf.x, cf.y);
        uint4 a = *(const uint4*)(ub + i8 * 8192 + SW(mo));
        uint4 bq = *(const uint4*)(ub + i8 * 8192 + SW(mo + 16));
        const __half2* pa = (const __half2*)&a;
        const __half2* pb = (const __half2*)&bq;
#pragma unroll
        for (int m = 0; m < 4; m++) {
            float2 f = __half22float2(pa[m]);
            ffma2(ta[m], cp, pack2(f.x, f.y));
        }
#pragma unroll
        for (int m = 0; m < 4; m++) {
            float2 f = __half22float2(pb[m]);
            ffma2(ta[4 + m], cp, pack2(f.x, f.y));
        }
        sh = __hadd2(sh, c2);
    }
    float* gt0 = g_t[IT - 1] + b0 * KD_ + myk * 16 + (lane & 1) * 8;
#pragma unroll
    for (int m = 0; m < 8; m++) {
        float lo, hi; unpack2(ta[m], lo, hi);
        atomicAdd(gt0 + m, lo);
        atomicAdd(gt0 + KD_ + m, hi);
    }
    if ((lane & 1) == 0) {
        float2 s = __half22float2(sh);
        atomicAdd(&g_S[IT - 2][b0 * K_ + myk], s.x);
        atomicAdd(&g_S[IT - 2][b1 * K_ + myk], s.y);
    }
}

// ---------------- final ----------------
__global__ void k_final(float* __restrict__ out) {
    const int idx = blockIdx.x * 256 + threadIdx.x;  // b*K + k
    const float inv = 1.0f / g_S[1][idx];
    const float4* tp = reinterpret_cast<const float4*>(&g_t[2][0] + idx * 16);
    float w[16]; float s2 = 0.f;
#pragma unroll
    for (int q = 0; q < 4; q++) {
        float4 tv = tp[q];
        w[q*4+0]=tv.x*inv; w[q*4+1]=tv.y*inv; w[q*4+2]=tv.z*inv; w[q*4+3]=tv.w*inv;
        s2 += w[q*4+0]*w[q*4+0] + w[q*4+1]*w[q*4+1] + w[q*4+2]*w[q*4+2] + w[q*4+3]*w[q*4+3];
    }
    float sc = sqrtf(s2) / (0.5f + s2);
    float4* op = reinterpret_cast<float4*>(out + idx * 16);
#pragma unroll
    for (int q = 0; q < 4; q++) {
        float4 o; o.x=sc*w[q*4+0]; o.y=sc*w[q*4+1]; o.z=sc*w[q*4+2]; o.w=sc*w[q*4+3];
        op[q] = o;
    }
    out[B_ * KD_ + idx] = s2 / (0.5f + s2);  // ||v||
}

// ---------------- launch ----------------
extern "C" void kernel_launch(void* const* d_in, const int* in_sizes, int n_in,
                              void* d_out, int out_size) {
    const float* x      = (const float*)d_in[0];
    const void*  labels = d_in[2];
    const float* W1     = (const float*)d_in[3];
    float*       out    = (float*)d_out;

    const int SMEM2 = 78848;   // ub 64K + cke 4K + vnp 1K + v1p 8K + pad
    const int SMEM3 = 88064;   // + vn2p 1K + v2p 8K
    cudaFuncSetAttribute((const void*)k_route<2>, cudaFuncAttributeMaxDynamicSharedMemorySize, SMEM2);
    cudaFuncSetAttribute((const void*)k_route<3>, cudaFuncAttributeMaxDynamicSharedMemorySize, SMEM3);

    k_init<<<768, 256>>>();
    k_pass1<<<dim3(128, 8), 256>>>(x, labels, W1);
    k_finalize<<<16, 256>>>(0);               // v0 = squash(sum_i u / 2048)
    k_route<2><<<4096, 256, SMEM2>>>();       // dd(v0) -> t1, S0
    k_finalize<<<16, 256>>>(1);               // v1 = squash(t1/S0)
    k_route<3><<<4096, 256, SMEM3>>>();       // dd(v0)+dd(v1) -> t2, S1
    k_final<<<16, 256>>>(out);                // poses + activations
    (void)in_sizes; (void)n_in; (void)out_size;
}

// round 8
// speedup vs baseline: 2.1769x; 2.1769x over previous
#include <cuda_runtime.h>
#include <cuda_fp16.h>
#include <cstdint>

#define B_  32
#define N_  2048
#define K_  128
#define CI_ 16
#define CO_ 16
#define KD_ (K_*CO_)   // 2048

typedef unsigned long long ull;

// XOR swizzle (SW128 style): permutes 16B cells within 1KB atoms -> conflict-free
#define SW(o) ((o) ^ (((o) >> 3) & 0x70))

// cp.async helpers
#define CP_ASYNC16(saddr, gptr) \
    asm volatile("cp.async.cg.shared.global [%0], [%1], 16;" :: "r"(saddr), "l"(gptr))
#define CP_COMMIT() asm volatile("cp.async.commit_group;")
#define CP_WAIT0()  asm volatile("cp.async.wait_group 0;" ::: "memory")

// ---------------- scratch (device globals; no allocation allowed) ----------------
__device__ __half g_uhat[(size_t)B_ * N_ * KD_];   // [b][i][k][d]  fp16, 268MB
__device__ float  g_t[3][B_ * KD_];                // per-iter weighted sums  [b][k][d]
__device__ float  g_S[2][B_ * K_];                 // per-iter coupling sums  [b][k]
__device__ float  g_v[2][B_ * KD_];                // v after iter1 / iter2   [b][k][d]
__device__ float  g_vn[2][B_ * K_];                // ||v||^2                 [b][k]

// ---------------- f32x2 packed helpers ----------------
__device__ __forceinline__ ull pack2(float a, float b) {
    ull r; asm("mov.b64 %0, {%1,%2};" : "=l"(r) : "f"(a), "f"(b)); return r;
}
__device__ __forceinline__ void unpack2(ull v, float& a, float& b) {
    asm("mov.b64 {%0,%1}, %2;" : "=f"(a), "=f"(b) : "l"(v));
}
__device__ __forceinline__ void ffma2(ull& d, ull a, ull b) {
    asm("fma.rn.f32x2 %0, %1, %2, %0;" : "+l"(d) : "l"(a), "l"(b));
}
__device__ __forceinline__ void fadd2(ull& d, ull a) {
    asm("add.rn.f32x2 %0, %0, %1;" : "+l"(d) : "l"(a));
}

// labels dtype-agnostic (int32 vs int64); labels = arange(128)
__device__ __forceinline__ int load_label(const void* labels, int k) {
    const int* p32 = (const int*)labels;
    if (p32[1] == 1) return p32[k];
    return (int)((const long long*)labels)[k];
}

// ---------------- init: zero accumulators ----------------
__global__ void k_init() {
    int idx = blockIdx.x * 256 + threadIdx.x;
    if (idx < 3 * B_ * KD_) (&g_t[0][0])[idx] = 0.f;
    if (idx < 2 * B_ * K_)  (&g_S[0][0])[idx] = 0.f;
}

// ---------------- pass 1: u_hat (fp32 compute, fp16 store) + t0 = sum_i u_hat ----
__global__ void __launch_bounds__(256, 2) k_pass1(const float* __restrict__ x,
                                                  const void* __restrict__ labels,
                                                  const float* __restrict__ W1) {
    __shared__ __align__(16) float xs[16 * 512];   // [i][(bp*16+c)*2 + (b&1)]
    const int tid = threadIdx.x;
    const int kd  = blockIdx.y * 256 + tid;        // 0..2047
    const int k   = kd >> 4;
    const int d   = kd & 15;
    int ksrc = load_label(labels, k);
    if ((unsigned)ksrc >= (unsigned)K_) ksrc = k;
    const int i0  = blockIdx.x * 16;

    for (int e = tid; e < 8192; e += 256) {
        const int b = e >> 8, rem = e & 255, i = rem >> 4, c = rem & 15;
        xs[i * 512 + ((b >> 1) * 16 + c) * 2 + (b & 1)] =
            x[((size_t)b * N_ + i0 + i) * CI_ + c];
    }
    __syncthreads();

    ull tsum[16];
#pragma unroll
    for (int bp = 0; bp < 16; bp++) tsum[bp] = 0ull;

    const size_t wstride4 = (size_t)K_ * CO_ * CI_ / 4;
    const float4* wp = reinterpret_cast<const float4*>(
        W1 + (((size_t)i0 * K_ + ksrc) * CO_ + d) * CI_);

    float4 cw0 = wp[0], cw1 = wp[1], cw2 = wp[2], cw3 = wp[3];
    const float4* np1 = wp + wstride4;
    float4 nw0 = np1[0], nw1 = np1[1], nw2 = np1[2], nw3 = np1[3];

    for (int ii = 0; ii < 16; ii++) {
        float4 mw0, mw1, mw2, mw3;
        if (ii < 14) {
            const float4* np = wp + (size_t)(ii + 2) * wstride4;
            mw0 = np[0]; mw1 = np[1]; mw2 = np[2]; mw3 = np[3];
        }
        ull wd[16];
        wd[0]=pack2(cw0.x,cw0.x); wd[1]=pack2(cw0.y,cw0.y); wd[2]=pack2(cw0.z,cw0.z); wd[3]=pack2(cw0.w,cw0.w);
        wd[4]=pack2(cw1.x,cw1.x); wd[5]=pack2(cw1.y,cw1.y); wd[6]=pack2(cw1.z,cw1.z); wd[7]=pack2(cw1.w,cw1.w);
        wd[8]=pack2(cw2.x,cw2.x); wd[9]=pack2(cw2.y,cw2.y); wd[10]=pack2(cw2.z,cw2.z); wd[11]=pack2(cw2.w,cw2.w);
        wd[12]=pack2(cw3.x,cw3.x); wd[13]=pack2(cw3.y,cw3.y); wd[14]=pack2(cw3.z,cw3.z); wd[15]=pack2(cw3.w,cw3.w);

        const int i = i0 + ii;
        __half* ubase = g_uhat + (size_t)i * KD_ + kd;
#pragma unroll
        for (int bp = 0; bp < 16; bp++) {
            const ulonglong2* xq = reinterpret_cast<const ulonglong2*>(xs + ii * 512 + bp * 32);
            ulonglong2 p0 = xq[0], p1 = xq[1], p2 = xq[2], p3 = xq[3];
            ulonglong2 p4 = xq[4], p5 = xq[5], p6 = xq[6], p7 = xq[7];
            ull acc0 = 0ull, acc1 = 0ull;
            ffma2(acc0, wd[0],  p0.x); ffma2(acc1, wd[1],  p0.y);
            ffma2(acc0, wd[2],  p1.x); ffma2(acc1, wd[3],  p1.y);
            ffma2(acc0, wd[4],  p2.x); ffma2(acc1, wd[5],  p2.y);
            ffma2(acc0, wd[6],  p3.x); ffma2(acc1, wd[7],  p3.y);
            ffma2(acc0, wd[8],  p4.x); ffma2(acc1, wd[9],  p4.y);
            ffma2(acc0, wd[10], p5.x); ffma2(acc1, wd[11], p5.y);
            ffma2(acc0, wd[12], p6.x); ffma2(acc1, wd[13], p6.y);
            ffma2(acc0, wd[14], p7.x); ffma2(acc1, wd[15], p7.y);
            fadd2(acc0, acc1);
            fadd2(tsum[bp], acc0);
            float lo, hi; unpack2(acc0, lo, hi);
            ubase[(size_t)(2 * bp)     * N_ * KD_] = __float2half_rn(lo);
            ubase[(size_t)(2 * bp + 1) * N_ * KD_] = __float2half_rn(hi);
        }
        cw0 = nw0; cw1 = nw1; cw2 = nw2; cw3 = nw3;
        nw0 = mw0; nw1 = mw1; nw2 = mw2; nw3 = mw3;
    }
#pragma unroll
    for (int bp = 0; bp < 16; bp++) {
        float a, bb; unpack2(tsum[bp], a, bb);
        atomicAdd(&g_t[0][(2 * bp)     * KD_ + kd], a);
        atomicAdd(&g_t[0][(2 * bp + 1) * KD_ + kd], bb);
    }
}

// ---------------- finalize: v[which] = squash(t * inv), vn[which] = ||v||^2 ------
__global__ void k_finalize(int which) {
    const int idx = blockIdx.x * 256 + threadIdx.x;   // b*K + k
    const float* t = g_t[which];
    float inv = (which == 0) ? (1.0f / 2048.0f) : (1.0f / g_S[0][idx]);
    const float4* tp = reinterpret_cast<const float4*>(t + idx * 16);
    float w[16]; float s2 = 0.f;
#pragma unroll
    for (int q = 0; q < 4; q++) {
        float4 tv = tp[q];
        w[q*4+0]=tv.x*inv; w[q*4+1]=tv.y*inv; w[q*4+2]=tv.z*inv; w[q*4+3]=tv.w*inv;
        s2 += w[q*4+0]*w[q*4+0] + w[q*4+1]*w[q*4+1] + w[q*4+2]*w[q*4+2] + w[q*4+3]*w[q*4+3];
    }
    float sc = sqrtf(s2) / (0.5f + s2);
    float4* vp = reinterpret_cast<float4*>(g_v[which] + idx * 16);
#pragma unroll
    for (int q = 0; q < 4; q++) {
        float4 o; o.x=sc*w[q*4+0]; o.y=sc*w[q*4+1]; o.z=sc*w[q*4+2]; o.w=sc*w[q*4+3];
        vp[q] = o;
    }
    g_vn[which][idx] = sc * sc * s2;
}

// ---------------- routing pass: half2 math, cp.async double buffer --------------
template <int IT>
__global__ void __launch_bounds__(256) k_route() {
    extern __shared__ __align__(128) char base[];
    float*   vn1 = (float*)base;                                   // 512B
    float*   vn2 = (float*)(base + 512);                           // 512B (IT3)
    char*    v1h = base + ((IT == 3) ? 1024 : 512);                // 4KB half2 v0
    char*    v2h = base + 5120;                                    // 4KB (IT3)
    __half2* cke = (__half2*)(base + ((IT == 3) ? 9216 : 4608));   // 4KB
    char*    ub  = base + ((IT == 3) ? 13312 : 8704);              // 2*32KB

    const int tid = threadIdx.x, lane = tid & 31, warp = tid >> 5;
    const int b   = blockIdx.x >> 6;
    const int ch  = blockIdx.x & 63;

    // stage v (convert fp32 -> half2), swizzled
    for (int e = tid; e < 1024; e += 256) {
        float2 f = *(const float2*)(g_v[0] + b * KD_ + 2 * e);
        *(__half2*)(v1h + SW(e * 4)) = __float22half2_rn(f);
        if (IT == 3) {
            float2 g = *(const float2*)(g_v[1] + b * KD_ + 2 * e);
            *(__half2*)(v2h + SW(e * 4)) = __float22half2_rn(g);
        }
    }
    if (tid < 128) {
        vn1[tid] = g_vn[0][b * K_ + tid];
        if (IT == 3) vn2[tid] = g_vn[1][b * K_ + tid];
    }

    const uint32_t ub_s = (uint32_t)__cvta_generic_to_shared(ub);

    // issue q=0 staging into buffer 0
    {
        const char* src = (const char*)(g_uhat + ((size_t)b * N_ + ch * 32 + warp) * KD_);
        uint32_t dst = ub_s + warp * 4096;
#pragma unroll
        for (int c = 0; c < 8; c++) {
            int off = (c * 32 + lane) * 16;
            CP_ASYNC16(dst + SW(off), src + off);
        }
        CP_COMMIT();
    }

    const int myk = warp * 16 + (lane >> 1);
    float tacc[8];
#pragma unroll
    for (int m = 0; m < 8; m++) tacc[m] = 0.f;
    float sacc = 0.f;

    int cur = 0;
    for (int q = 0; q < 4; q++) {
        CP_WAIT0();
        __syncthreads();

        if (q < 3) {
            const int inext = ch * 32 + (q + 1) * 8 + warp;
            const char* src = (const char*)(g_uhat + ((size_t)b * N_ + inext) * KD_);
            uint32_t dst = ub_s + (cur ^ 1) * 32768 + warp * 4096;
#pragma unroll
            for (int c = 0; c < 8; c++) {
                int off = (c * 32 + lane) * 16;
                CP_ASYNC16(dst + SW(off), src + off);
            }
            CP_COMMIT();
        }

        const char* msl = ub + cur * 32768 + warp * 4096;

        // ---- phase A: half2 s2/dot with DUAL chains, fp32 squash ----
        float lg[4];
#pragma unroll
        for (int j = 0; j < 4; j++) {
            const int k = lane + 32 * j;
            uint4 r0 = *(const uint4*)(msl + SW(k * 32));
            uint4 r1 = *(const uint4*)(msl + SW(k * 32 + 16));
            uint4 w0 = *(const uint4*)(v1h + SW(k * 32));
            uint4 w1 = *(const uint4*)(v1h + SW(k * 32 + 16));
            const __half2* u0 = (const __half2*)&r0;
            const __half2* u1 = (const __half2*)&r1;
            const __half2* a0 = (const __half2*)&w0;
            const __half2* a1 = (const __half2*)&w1;
            // dual accumulator chains (halve dependency depth)
            __half2 s2a = __hmul2(u0[0], u0[0]);
            __half2 s2b = __hmul2(u0[1], u0[1]);
            __half2 d1a = __hmul2(u0[0], a0[0]);
            __half2 d1b = __hmul2(u0[1], a0[1]);
            s2a = __hfma2(u0[2], u0[2], s2a);  d1a = __hfma2(u0[2], a0[2], d1a);
            s2b = __hfma2(u0[3], u0[3], s2b);  d1b = __hfma2(u0[3], a0[3], d1b);
            s2a = __hfma2(u1[0], u1[0], s2a);  d1a = __hfma2(u1[0], a1[0], d1a);
            s2b = __hfma2(u1[1], u1[1], s2b);  d1b = __hfma2(u1[1], a1[1], d1b);
            s2a = __hfma2(u1[2], u1[2], s2a);  d1a = __hfma2(u1[2], a1[2], d1a);
            s2b = __hfma2(u1[3], u1[3], s2b);  d1b = __hfma2(u1[3], a1[3], d1b);
            __half2 s2h = __hadd2(s2a, s2b);
            __half2 d1h = __hadd2(d1a, d1b);
            float dot2 = 0.f;
            if (IT == 3) {
                uint4 y0 = *(const uint4*)(v2h + SW(k * 32));
                uint4 y1 = *(const uint4*)(v2h + SW(k * 32 + 16));
                const __half2* b0 = (const __half2*)&y0;
                const __half2* b1 = (const __half2*)&y1;
                __half2 d2a = __hmul2(u0[0], b0[0]);
                __half2 d2b = __hmul2(u0[1], b0[1]);
                d2a = __hfma2(u0[2], b0[2], d2a);
                d2b = __hfma2(u0[3], b0[3], d2b);
                d2a = __hfma2(u1[0], b1[0], d2a);
                d2b = __hfma2(u1[1], b1[1], d2b);
                d2a = __hfma2(u1[2], b1[2], d2a);
                d2b = __hfma2(u1[3], b1[3], d2b);
                __half2 d2h = __hadd2(d2a, d2b);
                dot2 = __low2float(d2h) + __high2float(d2h);
            }
            float s2   = __low2float(s2h) + __high2float(s2h);
            float dot1 = __low2float(d1h) + __high2float(d1h);
            float sc = sqrtf(s2) / (0.5f + s2);
            float usq = sc * sc * s2;
            float dd = 1.f - (usq - 2.f * sc * dot1 + vn1[k]);
            if (IT == 3) dd += 1.f - (usq - 2.f * sc * dot2 + vn2[k]);
            lg[j] = dd;
        }
        // softmax WITHOUT max subtraction (logits bounded in [-6, 2] -> exp safe)
        float e0 = __expf(lg[0]), e1 = __expf(lg[1]), e2 = __expf(lg[2]), e3 = __expf(lg[3]);
        float ssum = (e0 + e1) + (e2 + e3);
#pragma unroll
        for (int o = 16; o > 0; o >>= 1) ssum += __shfl_xor_sync(0xffffffffu, ssum, o);
        const float invs = 1.f / ssum;
        cke[warp * 128 + lane +  0] = __float2half2_rn(e0 * invs);
        cke[warp * 128 + lane + 32] = __float2half2_rn(e1 * invs);
        cke[warp * 128 + lane + 64] = __float2half2_rn(e2 * invs);
        cke[warp * 128 + lane + 96] = __float2half2_rn(e3 * invs);

        __syncthreads();   // c + all slices ready for phase B

        // ---- phase B: half2 register accumulation over this 8-i group ----
        const char* bb = ub + cur * 32768;
        const int boff = warp * 512 + lane * 16;
        __half2 t0 = __float2half2_rn(0.f), t1 = t0, t2 = t0, t3 = t0, sh = t0;
#pragma unroll
        for (int i8 = 0; i8 < 8; i8++) {
            __half2 c2 = cke[i8 * 128 + myk];
            uint4 uv = *(const uint4*)(bb + i8 * 4096 + SW(boff));
            const __half2* u2 = (const __half2*)&uv;
            t0 = __hfma2(u2[0], c2, t0);
            t1 = __hfma2(u2[1], c2, t1);
            t2 = __hfma2(u2[2], c2, t2);
            t3 = __hfma2(u2[3], c2, t3);
            sh = __hadd2(sh, c2);
        }
        tacc[0] += __low2float(t0); tacc[1] += __high2float(t0);
        tacc[2] += __low2float(t1); tacc[3] += __high2float(t1);
        tacc[4] += __low2float(t2); tacc[5] += __high2float(t2);
        tacc[6] += __low2float(t3); tacc[7] += __high2float(t3);
        sacc += __low2float(sh);
        cur ^= 1;
    }

    float* gt = g_t[IT - 1] + b * KD_ + myk * 16 + (lane & 1) * 8;
#pragma unroll
    for (int m = 0; m < 8; m++) atomicAdd(gt + m, tacc[m]);
    if ((lane & 1) == 0) atomicAdd(&g_S[IT - 2][b * K_ + myk], sacc);
}

// ---------------- final: poses + activations -> d_out ----------------
__global__ void k_final(float* __restrict__ out) {
    const int idx = blockIdx.x * 256 + threadIdx.x;  // b*K + k
    const float inv = 1.0f / g_S[1][idx];
    const float4* tp = reinterpret_cast<const float4*>(&g_t[2][0] + idx * 16);
    float w[16]; float s2 = 0.f;
#pragma unroll
    for (int q = 0; q < 4; q++) {
        float4 tv = tp[q];
        w[q*4+0]=tv.x*inv; w[q*4+1]=tv.y*inv; w[q*4+2]=tv.z*inv; w[q*4+3]=tv.w*inv;
        s2 += w[q*4+0]*w[q*4+0] + w[q*4+1]*w[q*4+1] + w[q*4+2]*w[q*4+2] + w[q*4+3]*w[q*4+3];
    }
    float sc = sqrtf(s2) / (0.5f + s2);
    float4* op = reinterpret_cast<float4*>(out + idx * 16);
#pragma unroll
    for (int q = 0; q < 4; q++) {
        float4 o; o.x=sc*w[q*4+0]; o.y=sc*w[q*4+1]; o.z=sc*w[q*4+2]; o.w=sc*w[q*4+3];
        op[q] = o;
    }
    out[B_ * KD_ + idx] = s2 / (0.5f + s2);  // ||v||
}

// ---------------- launch ----------------
extern "C" void kernel_launch(void* const* d_in, const int* in_sizes, int n_in,
                              void* d_out, int out_size) {
    const float* x      = (const float*)d_in[0];
    const void*  labels = d_in[2];
    const float* W1     = (const float*)d_in[3];
    float*       out    = (float*)d_out;

    const int SMEM2 = 8704  + 2 * 32768;   // 74240
    const int SMEM3 = 13312 + 2 * 32768;   // 78848
    cudaFuncSetAttribute((const void*)k_route<2>, cudaFuncAttributeMaxDynamicSharedMemorySize, SMEM2);
    cudaFuncSetAttribute((const void*)k_route<3>, cudaFuncAttributeMaxDynamicSharedMemorySize, SMEM3);

    k_init<<<768, 256>>>();
    k_pass1<<<dim3(128, 8), 256>>>(x, labels, W1);
    k_finalize<<<16, 256>>>(0);               // v0 = squash(sum_i u / 2048)
    k_route<2><<<2048, 256, SMEM2>>>();       // dd(v0) -> t1, S0
    k_finalize<<<16, 256>>>(1);               // v1 = squash(t1/S0)
    k_route<3><<<2048, 256, SMEM3>>>();       // dd(v0)+dd(v1) -> t2, S1
    k_final<<<16, 256>>>(out);                // poses + activations
    (void)in_sizes; (void)n_in; (void)out_size;
}

// round 9
// speedup vs baseline: 2.1837x; 1.0031x over previous
#include <cuda_runtime.h>
#include <cuda_fp16.h>
#include <cstdint>

#define B_  32
#define N_  2048
#define K_  128
#define CI_ 16
#define CO_ 16
#define KD_ (K_*CO_)   // 2048

typedef unsigned long long ull;

// XOR swizzle: permutes 16B cells within 1KB atoms -> conflict-free
#define SW(o) ((o) ^ (((o) >> 3) & 0x70))

// cp.async helpers (per-thread groups -> per-warp private pipelines)
#define CP_ASYNC16(saddr, gptr) \
    asm volatile("cp.async.cg.shared.global [%0], [%1], 16;" :: "r"(saddr), "l"(gptr))
#define CP_COMMIT() asm volatile("cp.async.commit_group;")
#define CP_WAIT0()  asm volatile("cp.async.wait_group 0;" ::: "memory")
#define CP_WAIT1()  asm volatile("cp.async.wait_group 1;" ::: "memory")

// ---------------- scratch (device globals; no allocation allowed) ----------------
__device__ __half g_uhat[(size_t)B_ * N_ * KD_];   // [b][i][k][d]  fp16, 268MB
__device__ float  g_t[3][B_ * KD_];
__device__ float  g_S[2][B_ * K_];
__device__ float  g_v[2][B_ * KD_];
__device__ float  g_vn[2][B_ * K_];

// ---------------- f32x2 packed helpers ----------------
__device__ __forceinline__ ull pack2(float a, float b) {
    ull r; asm("mov.b64 %0, {%1,%2};" : "=l"(r) : "f"(a), "f"(b)); return r;
}
__device__ __forceinline__ void unpack2(ull v, float& a, float& b) {
    asm("mov.b64 {%0,%1}, %2;" : "=f"(a), "=f"(b) : "l"(v));
}
__device__ __forceinline__ void ffma2(ull& d, ull a, ull b) {
    asm("fma.rn.f32x2 %0, %1, %2, %0;" : "+l"(d) : "l"(a), "l"(b));
}
__device__ __forceinline__ void fadd2(ull& d, ull a) {
    asm("add.rn.f32x2 %0, %0, %1;" : "+l"(d) : "l"(a));
}

// labels dtype-agnostic (int32 vs int64); labels = arange(128)
__device__ __forceinline__ int load_label(const void* labels, int k) {
    const int* p32 = (const int*)labels;
    if (p32[1] == 1) return p32[k];
    return (int)((const long long*)labels)[k];
}

// ---------------- init ----------------
__global__ void k_init() {
    int idx = blockIdx.x * 256 + threadIdx.x;
    if (idx < 3 * B_ * KD_) (&g_t[0][0])[idx] = 0.f;
    if (idx < 2 * B_ * K_)  (&g_S[0][0])[idx] = 0.f;
}

// ---------------- pass 1 (unchanged from R8) ----------------
__global__ void __launch_bounds__(256, 2) k_pass1(const float* __restrict__ x,
                                                  const void* __restrict__ labels,
                                                  const float* __restrict__ W1) {
    __shared__ __align__(16) float xs[16 * 512];
    const int tid = threadIdx.x;
    const int kd  = blockIdx.y * 256 + tid;
    const int k   = kd >> 4;
    const int d   = kd & 15;
    int ksrc = load_label(labels, k);
    if ((unsigned)ksrc >= (unsigned)K_) ksrc = k;
    const int i0  = blockIdx.x * 16;

    for (int e = tid; e < 8192; e += 256) {
        const int b = e >> 8, rem = e & 255, i = rem >> 4, c = rem & 15;
        xs[i * 512 + ((b >> 1) * 16 + c) * 2 + (b & 1)] =
            x[((size_t)b * N_ + i0 + i) * CI_ + c];
    }
    __syncthreads();

    ull tsum[16];
#pragma unroll
    for (int bp = 0; bp < 16; bp++) tsum[bp] = 0ull;

    const size_t wstride4 = (size_t)K_ * CO_ * CI_ / 4;
    const float4* wp = reinterpret_cast<const float4*>(
        W1 + (((size_t)i0 * K_ + ksrc) * CO_ + d) * CI_);

    float4 cw0 = wp[0], cw1 = wp[1], cw2 = wp[2], cw3 = wp[3];
    const float4* np1 = wp + wstride4;
    float4 nw0 = np1[0], nw1 = np1[1], nw2 = np1[2], nw3 = np1[3];

    for (int ii = 0; ii < 16; ii++) {
        float4 mw0, mw1, mw2, mw3;
        if (ii < 14) {
            const float4* np = wp + (size_t)(ii + 2) * wstride4;
            mw0 = np[0]; mw1 = np[1]; mw2 = np[2]; mw3 = np[3];
        }
        ull wd[16];
        wd[0]=pack2(cw0.x,cw0.x); wd[1]=pack2(cw0.y,cw0.y); wd[2]=pack2(cw0.z,cw0.z); wd[3]=pack2(cw0.w,cw0.w);
        wd[4]=pack2(cw1.x,cw1.x); wd[5]=pack2(cw1.y,cw1.y); wd[6]=pack2(cw1.z,cw1.z); wd[7]=pack2(cw1.w,cw1.w);
        wd[8]=pack2(cw2.x,cw2.x); wd[9]=pack2(cw2.y,cw2.y); wd[10]=pack2(cw2.z,cw2.z); wd[11]=pack2(cw2.w,cw2.w);
        wd[12]=pack2(cw3.x,cw3.x); wd[13]=pack2(cw3.y,cw3.y); wd[14]=pack2(cw3.z,cw3.z); wd[15]=pack2(cw3.w,cw3.w);

        const int i = i0 + ii;
        __half* ubase = g_uhat + (size_t)i * KD_ + kd;
#pragma unroll
        for (int bp = 0; bp < 16; bp++) {
            const ulonglong2* xq = reinterpret_cast<const ulonglong2*>(xs + ii * 512 + bp * 32);
            ulonglong2 p0 = xq[0], p1 = xq[1], p2 = xq[2], p3 = xq[3];
            ulonglong2 p4 = xq[4], p5 = xq[5], p6 = xq[6], p7 = xq[7];
            ull acc0 = 0ull, acc1 = 0ull;
            ffma2(acc0, wd[0],  p0.x); ffma2(acc1, wd[1],  p0.y);
            ffma2(acc0, wd[2],  p1.x); ffma2(acc1, wd[3],  p1.y);
            ffma2(acc0, wd[4],  p2.x); ffma2(acc1, wd[5],  p2.y);
            ffma2(acc0, wd[6],  p3.x); ffma2(acc1, wd[7],  p3.y);
            ffma2(acc0, wd[8],  p4.x); ffma2(acc1, wd[9],  p4.y);
            ffma2(acc0, wd[10], p5.x); ffma2(acc1, wd[11], p5.y);
            ffma2(acc0, wd[12], p6.x); ffma2(acc1, wd[13], p6.y);
            ffma2(acc0, wd[14], p7.x); ffma2(acc1, wd[15], p7.y);
            fadd2(acc0, acc1);
            fadd2(tsum[bp], acc0);
            float lo, hi; unpack2(acc0, lo, hi);
            ubase[(size_t)(2 * bp)     * N_ * KD_] = __float2half_rn(lo);
            ubase[(size_t)(2 * bp + 1) * N_ * KD_] = __float2half_rn(hi);
        }
        cw0 = nw0; cw1 = nw1; cw2 = nw2; cw3 = nw3;
        nw0 = mw0; nw1 = mw1; nw2 = mw2; nw3 = mw3;
    }
#pragma unroll
    for (int bp = 0; bp < 16; bp++) {
        float a, bb; unpack2(tsum[bp], a, bb);
        atomicAdd(&g_t[0][(2 * bp)     * KD_ + kd], a);
        atomicAdd(&g_t[0][(2 * bp + 1) * KD_ + kd], bb);
    }
}

// ---------------- finalize ----------------
__global__ void k_finalize(int which) {
    const int idx = blockIdx.x * 256 + threadIdx.x;
    const float* t = g_t[which];
    float inv = (which == 0) ? (1.0f / 2048.0f) : (1.0f / g_S[0][idx]);
    const float4* tp = reinterpret_cast<const float4*>(t + idx * 16);
    float w[16]; float s2 = 0.f;
#pragma unroll
    for (int q = 0; q < 4; q++) {
        float4 tv = tp[q];
        w[q*4+0]=tv.x*inv; w[q*4+1]=tv.y*inv; w[q*4+2]=tv.z*inv; w[q*4+3]=tv.w*inv;
        s2 += w[q*4+0]*w[q*4+0] + w[q*4+1]*w[q*4+1] + w[q*4+2]*w[q*4+2] + w[q*4+3]*w[q*4+3];
    }
    float sc = sqrtf(s2) / (0.5f + s2);
    float4* vp = reinterpret_cast<float4*>(g_v[which] + idx * 16);
#pragma unroll
    for (int q = 0; q < 4; q++) {
        float4 o; o.x=sc*w[q*4+0]; o.y=sc*w[q*4+1]; o.z=sc*w[q*4+2]; o.w=sc*w[q*4+3];
        vp[q] = o;
    }
    g_vn[which][idx] = sc * sc * s2;
}

// ---------------- routing pass: warp-private pipeline, zero in-loop barriers ----
// grid 2048 (32 b * 64 chunks of 32 i); block 256 (8 warps, warp w owns i-range
// ch*32 + w*4 + q, q=0..3). Each warp: private cp.async depth-2 double buffer;
// u slice lives in registers for dd + softmax + t-accumulation; block merges the
// 8 warp-partials once at the end via SMEM tree-reduce.
template <int IT>
__global__ void __launch_bounds__(256, 2) k_route() {
    extern __shared__ __align__(128) char base[];
    float* vn1 = (float*)base;                                // 512B
    float* vn2 = (float*)(base + 512);                        // IT3
    char*  v1h = base + ((IT == 3) ? 1024 : 512);             // 4KB half2 v0 (swizzled)
    char*  v2h = base + 5120;                                 // IT3: 4KB
    char*  ub  = base + ((IT == 3) ? 9216 : 4608);            // 2 x 8 x 4KB u slices
    // reduction area reuses ub after the final barrier:
    const int TPITCH = 4132;                                  // per-warp t block (bank-staggered)
    const int SOFF   = 8 * TPITCH;                            // 33056: S area, pitch 516

    const int tid = threadIdx.x, lane = tid & 31, warp = tid >> 5;
    const int b   = blockIdx.x >> 6;
    const int ch  = blockIdx.x & 63;
    const int ibase = ch * 32 + warp * 4;

    const uint32_t ub_s = (uint32_t)__cvta_generic_to_shared(ub);
    const uint32_t bufA = ub_s + warp * 4096;
    const uint32_t bufB = ub_s + 32768 + warp * 4096;

    // issue q0 -> A, q1 -> B immediately (per-thread groups)
    {
        const char* s0 = (const char*)(g_uhat + ((size_t)b * N_ + ibase + 0) * KD_);
        const char* s1 = (const char*)(g_uhat + ((size_t)b * N_ + ibase + 1) * KD_);
#pragma unroll
        for (int c = 0; c < 8; c++) {
            int off = (c * 32 + lane) * 16;
            CP_ASYNC16(bufA + SW(off), s0 + off);
        }
        CP_COMMIT();
#pragma unroll
        for (int c = 0; c < 8; c++) {
            int off = (c * 32 + lane) * 16;
            CP_ASYNC16(bufB + SW(off), s1 + off);
        }
        CP_COMMIT();
    }

    // cooperative v staging (overlaps the transfers)
    for (int e = tid; e < 1024; e += 256) {
        float2 f = *(const float2*)(g_v[0] + b * KD_ + 2 * e);
        *(__half2*)(v1h + SW(e * 4)) = __float22half2_rn(f);
        if (IT == 3) {
            float2 g = *(const float2*)(g_v[1] + b * KD_ + 2 * e);
            *(__half2*)(v2h + SW(e * 4)) = __float22half2_rn(g);
        }
    }
    if (tid < 128) {
        vn1[tid] = g_vn[0][b * K_ + tid];
        if (IT == 3) vn2[tid] = g_vn[1][b * K_ + tid];
    }
    __syncthreads();   // v visible to all; ub regions are warp-private

    // per-warp accumulators: t[j][m] = half2(d=2m, 2m+1) for k = lane + 32j
    __half2 tq[4][8];
#pragma unroll
    for (int j = 0; j < 4; j++)
#pragma unroll
        for (int m = 0; m < 8; m++) tq[j][m] = __float2half2_rn(0.f);
    float sacc[4] = {0.f, 0.f, 0.f, 0.f};

    char* ubg = ub;   // generic pointer base for reads

#pragma unroll
    for (int q = 0; q < 4; q++) {
        if (q < 3) { CP_WAIT1(); } else { CP_WAIT0(); }
        __syncwarp();   // cross-lane visibility of this warp's slice

        const char* msl = ubg + ((q & 1) ? 32768 : 0) + warp * 4096;

        // load entire slice into registers + compute logits
        uint4 ur[8];
        float lg[4];
#pragma unroll
        for (int j = 0; j < 4; j++) {
            const int k = lane + 32 * j;
            ur[2*j]   = *(const uint4*)(msl + SW(k * 32));
            ur[2*j+1] = *(const uint4*)(msl + SW(k * 32 + 16));
            uint4 w0 = *(const uint4*)(v1h + SW(k * 32));
            uint4 w1 = *(const uint4*)(v1h + SW(k * 32 + 16));
            const __half2* u0 = (const __half2*)&ur[2*j];
            const __half2* u1 = (const __half2*)&ur[2*j+1];
            const __half2* a0 = (const __half2*)&w0;
            const __half2* a1 = (const __half2*)&w1;
            __half2 s2a = __hmul2(u0[0], u0[0]);
            __half2 s2b = __hmul2(u0[1], u0[1]);
            __half2 d1a = __hmul2(u0[0], a0[0]);
            __half2 d1b = __hmul2(u0[1], a0[1]);
            s2a = __hfma2(u0[2], u0[2], s2a);  d1a = __hfma2(u0[2], a0[2], d1a);
            s2b = __hfma2(u0[3], u0[3], s2b);  d1b = __hfma2(u0[3], a0[3], d1b);
            s2a = __hfma2(u1[0], u1[0], s2a);  d1a = __hfma2(u1[0], a1[0], d1a);
            s2b = __hfma2(u1[1], u1[1], s2b);  d1b = __hfma2(u1[1], a1[1], d1b);
            s2a = __hfma2(u1[2], u1[2], s2a);  d1a = __hfma2(u1[2], a1[2], d1a);
            s2b = __hfma2(u1[3], u1[3], s2b);  d1b = __hfma2(u1[3], a1[3], d1b);
            __half2 s2h = __hadd2(s2a, s2b);
            __half2 d1h = __hadd2(d1a, d1b);
            float dot2 = 0.f;
            if (IT == 3) {
                uint4 y0 = *(const uint4*)(v2h + SW(k * 32));
                uint4 y1 = *(const uint4*)(v2h + SW(k * 32 + 16));
                const __half2* b0 = (const __half2*)&y0;
                const __half2* b1 = (const __half2*)&y1;
                __half2 d2a = __hmul2(u0[0], b0[0]);
                __half2 d2b = __hmul2(u0[1], b0[1]);
                d2a = __hfma2(u0[2], b0[2], d2a);
                d2b = __hfma2(u0[3], b0[3], d2b);
                d2a = __hfma2(u1[0], b1[0], d2a);
                d2b = __hfma2(u1[1], b1[1], d2b);
                d2a = __hfma2(u1[2], b1[2], d2a);
                d2b = __hfma2(u1[3], b1[3], d2b);
                __half2 d2h = __hadd2(d2a, d2b);
                dot2 = __low2float(d2h) + __high2float(d2h);
            }
            float s2   = __low2float(s2h) + __high2float(s2h);
            float dot1 = __low2float(d1h) + __high2float(d1h);
            float sc = sqrtf(s2) / (0.5f + s2);
            float usq = sc * sc * s2;
            float dd = 1.f - (usq - 2.f * sc * dot1 + vn1[k]);
            if (IT == 3) dd += 1.f - (usq - 2.f * sc * dot2 + vn2[k]);
            lg[j] = dd;
        }

        // slice fully in registers -> refill this buffer for q+2
        __syncwarp();
        if (q < 2) {
            const char* sn = (const char*)(g_uhat + ((size_t)b * N_ + ibase + q + 2) * KD_);
            uint32_t dst = (q & 1) ? bufB : bufA;
#pragma unroll
            for (int c = 0; c < 8; c++) {
                int off = (c * 32 + lane) * 16;
                CP_ASYNC16(dst + SW(off), sn + off);
            }
            CP_COMMIT();
        }

        // softmax over 128 k (no max-subtract: logits bounded)
        float e0 = __expf(lg[0]), e1 = __expf(lg[1]), e2 = __expf(lg[2]), e3 = __expf(lg[3]);
        float ssum = (e0 + e1) + (e2 + e3);
#pragma unroll
        for (int o = 16; o > 0; o >>= 1) ssum += __shfl_xor_sync(0xffffffffu, ssum, o);
        const float invs = 1.f / ssum;
        float ee[4] = {e0, e1, e2, e3};

        // accumulate t and S (warp-private, registers only)
#pragma unroll
        for (int j = 0; j < 4; j++) {
            __half ch = __float2half_rn(ee[j] * invs);
            __half2 c2 = __half2half2(ch);
            const __half2* u0 = (const __half2*)&ur[2*j];
            const __half2* u1 = (const __half2*)&ur[2*j+1];
            tq[j][0] = __hfma2(u0[0], c2, tq[j][0]);
            tq[j][1] = __hfma2(u0[1], c2, tq[j][1]);
            tq[j][2] = __hfma2(u0[2], c2, tq[j][2]);
            tq[j][3] = __hfma2(u0[3], c2, tq[j][3]);
            tq[j][4] = __hfma2(u1[0], c2, tq[j][4]);
            tq[j][5] = __hfma2(u1[1], c2, tq[j][5]);
            tq[j][6] = __hfma2(u1[2], c2, tq[j][6]);
            tq[j][7] = __hfma2(u1[3], c2, tq[j][7]);
            sacc[j] += __half2float(ch);
        }
    }

    // ---- merge 8 warp-partials: write to SMEM (reusing ub), tree-reduce ----
    __syncthreads();   // all warps done with ub
#pragma unroll
    for (int j = 0; j < 4; j++) {
        const int k = lane + 32 * j;
#pragma unroll
        for (int m = 0; m < 8; m++)
            *(__half2*)(ubg + warp * TPITCH + m * 512 + k * 4) = tq[j][m];
        *(float*)(ubg + SOFF + warp * 516 + k * 4) = sacc[j];
    }
    __syncthreads();

    // t reduce: 1024 (m,k) half2-columns, 4 per thread
    float* gt = g_t[IT - 1] + b * KD_;
#pragma unroll
    for (int t4 = 0; t4 < 4; t4++) {
        const int col = tid + t4 * 256;
        const int m = col >> 7, k = col & 127;
        float sx = 0.f, sy = 0.f;
#pragma unroll
        for (int w = 0; w < 8; w++) {
            __half2 h = *(const __half2*)(ubg + w * TPITCH + m * 512 + k * 4);
            float2 f = __half22float2(h);
            sx += f.x; sy += f.y;
        }
        atomicAdd(gt + k * 16 + 2 * m,     sx);
        atomicAdd(gt + k * 16 + 2 * m + 1, sy);
    }
    if (tid < 128) {
        float s = 0.f;
#pragma unroll
        for (int w = 0; w < 8; w++)
            s += *(const float*)(ubg + SOFF + w * 516 + tid * 4);
        atomicAdd(&g_S[IT - 2][b * K_ + tid], s);
    }
}

// ---------------- final ----------------
__global__ void k_final(float* __restrict__ out) {
    const int idx = blockIdx.x * 256 + threadIdx.x;
    const float inv = 1.0f / g_S[1][idx];
    const float4* tp = reinterpret_cast<const float4*>(&g_t[2][0] + idx * 16);
    float w[16]; float s2 = 0.f;
#pragma unroll
    for (int q = 0; q < 4; q++) {
        float4 tv = tp[q];
        w[q*4+0]=tv.x*inv; w[q*4+1]=tv.y*inv; w[q*4+2]=tv.z*inv; w[q*4+3]=tv.w*inv;
        s2 += w[q*4+0]*w[q*4+0] + w[q*4+1]*w[q*4+1] + w[q*4+2]*w[q*4+2] + w[q*4+3]*w[q*4+3];
    }
    float sc = sqrtf(s2) / (0.5f + s2);
    float4* op = reinterpret_cast<float4*>(out + idx * 16);
#pragma unroll
    for (int q = 0; q < 4; q++) {
        float4 o; o.x=sc*w[q*4+0]; o.y=sc*w[q*4+1]; o.z=sc*w[q*4+2]; o.w=sc*w[q*4+3];
        op[q] = o;
    }
    out[B_ * KD_ + idx] = s2 / (0.5f + s2);  // ||v||
}

// ---------------- launch ----------------
extern "C" void kernel_launch(void* const* d_in, const int* in_sizes, int n_in,
                              void* d_out, int out_size) {
    const float* x      = (const float*)d_in[0];
    const void*  labels = d_in[2];
    const float* W1     = (const float*)d_in[3];
    float*       out    = (float*)d_out;

    const int SMEM2 = 4608 + 65536;    // 70144
    const int SMEM3 = 9216 + 65536;    // 74752
    cudaFuncSetAttribute((const void*)k_route<2>, cudaFuncAttributeMaxDynamicSharedMemorySize, SMEM2);
    cudaFuncSetAttribute((const void*)k_route<3>, cudaFuncAttributeMaxDynamicSharedMemorySize, SMEM3);

    k_init<<<768, 256>>>();
    k_pass1<<<dim3(128, 8), 256>>>(x, labels, W1);
    k_finalize<<<16, 256>>>(0);               // v0 = squash(sum_i u / 2048)
    k_route<2><<<2048, 256, SMEM2>>>();       // dd(v0) -> t1, S0
    k_finalize<<<16, 256>>>(1);               // v1 = squash(t1/S0)
    k_route<3><<<2048, 256, SMEM3>>>();       // dd(v0)+dd(v1) -> t2, S1
    k_final<<<16, 256>>>(out);                // poses + activations
    (void)in_sizes; (void)n_in; (void)out_size;
}